// round 2
// baseline (speedup 1.0000x reference)
#include <cuda_runtime.h>
#include <cstdint>

// Problem constants
#define M_DIM 4096
#define N_DIM 32000
#define K_DIM 128
#define BM 128
#define BN 256
#define KP 132   // padded k-stride in smem words (132 % 32 == 4 -> conflict-free)

// Device scratch
__device__ float g_summed[M_DIM * K_DIM];          // 2 MB (TF32-rounded A)
__device__ int   g_stride;                         // 1 = int32 indices, 2 = int64

__device__ __forceinline__ unsigned f2tf32(float f) {
    unsigned u;
    asm("cvt.rna.tf32.f32 %0, %1;" : "=r"(u) : "f"(f));
    return u;
}

// ---------------------------------------------------------------------------
// Detect int64 vs int32 index tensor (odd 32-bit words all zero => int64).
// ---------------------------------------------------------------------------
__global__ void detect_kernel(const int* __restrict__ x32) {
    __shared__ int any;
    if (threadIdx.x == 0) any = 0;
    __syncthreads();
    int found = 0;
    for (int i = 1 + 2 * threadIdx.x; i < 32768; i += 512)
        if (x32[i] != 0) found = 1;
    if (found) any = 1;
    __syncthreads();
    if (threadIdx.x == 0) g_stride = any ? 1 : 2;
}

// ---------------------------------------------------------------------------
// CBOW gather-sum (padding_idx=0 skipped), TF32-rounded output.
// One warp per sample, float4 per lane.
// ---------------------------------------------------------------------------
__global__ void sum_emb_kernel(const int* __restrict__ x32,
                               const float4* __restrict__ emb) {
    int sample = blockIdx.x * 8 + (threadIdx.x >> 5);
    int v = threadIdx.x & 31;
    int stride = g_stride;
    float4 s = make_float4(0.f, 0.f, 0.f, 0.f);
#pragma unroll
    for (int c = 0; c < 8; c++) {
        int i = x32[(sample * 8 + c) * stride];
        if (i != 0) {
            float4 t = emb[i * 32 + v];
            s.x += t.x; s.y += t.y; s.z += t.z; s.w += t.w;
        }
    }
    uint4 u;
    u.x = f2tf32(s.x); u.y = f2tf32(s.y);
    u.z = f2tf32(s.z); u.w = f2tf32(s.w);
    reinterpret_cast<uint4*>(g_summed)[sample * 32 + v] = u;
}

// ---------------------------------------------------------------------------
// GEMM: out[M,N] = summed[M,K] @ W[N,K]^T + b
// CTA 128x256, 512 threads, 16 warps in 4(M)x4(N) grid, 32x64 per warp.
// W is TF32-rounded on the fly during the B-tile fill (no scratch copy).
// Smem: A[128][132] + B[256][132] = 202,752 B (1 CTA/SM, 16 warps).
// ---------------------------------------------------------------------------
__global__ void __launch_bounds__(512, 1)
gemm_kernel(const float* __restrict__ W, const float* __restrict__ bias,
            float* __restrict__ out) {
    extern __shared__ unsigned smem[];
    unsigned* As = smem;              // [128][132]
    unsigned* Bs = smem + BM * KP;    // [256][132]

    const int tid = threadIdx.x;
    const int bm = blockIdx.y * BM;
    const int bn = blockIdx.x * BN;

    // Fill A tile: 128 rows x 32 uint4 (already TF32-rounded)
    const uint4* Ag = reinterpret_cast<const uint4*>(g_summed) + bm * 32;
#pragma unroll
    for (int it = 0; it < 8; it++) {
        int idx = tid + it * 512;
        int row = idx >> 5, j = idx & 31;
        uint4 v = Ag[idx];
        *reinterpret_cast<uint4*>(&As[row * KP + j * 4]) = v;
    }
    // Fill B tile from W directly, rounding to TF32 inline: 256 rows x 32 float4
    const float4* Wg = reinterpret_cast<const float4*>(W) + bn * 32;
#pragma unroll
    for (int it = 0; it < 16; it++) {
        int idx = tid + it * 512;
        int row = idx >> 5, j = idx & 31;
        float4 v = Wg[idx];
        uint4 u;
        u.x = f2tf32(v.x); u.y = f2tf32(v.y);
        u.z = f2tf32(v.z); u.w = f2tf32(v.w);
        *reinterpret_cast<uint4*>(&Bs[row * KP + j * 4]) = u;
    }
    __syncthreads();

    const int lane = tid & 31;
    const int warp = tid >> 5;
    const int wm = (warp & 3) * 32;    // 4 warps along M
    const int wn = (warp >> 2) * 64;   // 4 warps along N
    const int g  = lane >> 2;          // 0..7
    const int tg = lane & 3;           // 0..3

    float acc[2][8][4];
#pragma unroll
    for (int mi = 0; mi < 2; mi++)
#pragma unroll
        for (int ni = 0; ni < 8; ni++)
#pragma unroll
            for (int r = 0; r < 4; r++) acc[mi][ni][r] = 0.f;

#pragma unroll 2
    for (int ks = 0; ks < 16; ks++) {
        int k0 = ks * 8;
        unsigned a[2][4], b[8][2];
#pragma unroll
        for (int mi = 0; mi < 2; mi++) {
            int r0 = (wm + mi * 16 + g) * KP + k0 + tg;
            a[mi][0] = As[r0];
            a[mi][1] = As[r0 + 8 * KP];
            a[mi][2] = As[r0 + 4];
            a[mi][3] = As[r0 + 8 * KP + 4];
        }
#pragma unroll
        for (int ni = 0; ni < 8; ni++) {
            int c0 = (wn + ni * 8 + g) * KP + k0 + tg;
            b[ni][0] = Bs[c0];
            b[ni][1] = Bs[c0 + 4];
        }
#pragma unroll
        for (int mi = 0; mi < 2; mi++)
#pragma unroll
            for (int ni = 0; ni < 8; ni++)
                asm volatile(
                    "mma.sync.aligned.m16n8k8.row.col.f32.tf32.tf32.f32 "
                    "{%0,%1,%2,%3}, {%4,%5,%6,%7}, {%8,%9}, {%0,%1,%2,%3};"
                    : "+f"(acc[mi][ni][0]), "+f"(acc[mi][ni][1]),
                      "+f"(acc[mi][ni][2]), "+f"(acc[mi][ni][3])
                    : "r"(a[mi][0]), "r"(a[mi][1]), "r"(a[mi][2]), "r"(a[mi][3]),
                      "r"(b[ni][0]), "r"(b[ni][1]));
    }

    // Epilogue: bias add + float2 stores. Tiles divide exactly; no bounds checks.
#pragma unroll
    for (int ni = 0; ni < 8; ni++) {
        int col = bn + wn + ni * 8 + 2 * tg;
        float2 bb = *reinterpret_cast<const float2*>(bias + col);
#pragma unroll
        for (int mi = 0; mi < 2; mi++) {
            int row = bm + wm + mi * 16 + g;
            float2 v0 = make_float2(acc[mi][ni][0] + bb.x, acc[mi][ni][1] + bb.y);
            float2 v1 = make_float2(acc[mi][ni][2] + bb.x, acc[mi][ni][3] + bb.y);
            *reinterpret_cast<float2*>(out + (size_t)row * N_DIM + col) = v0;
            *reinterpret_cast<float2*>(out + (size_t)(row + 8) * N_DIM + col) = v1;
        }
    }
}

// ---------------------------------------------------------------------------
extern "C" void kernel_launch(void* const* d_in, const int* in_sizes, int n_in,
                              void* d_out, int out_size) {
    const int*   x    = (const int*)d_in[0];
    const float* emb  = (const float*)d_in[1];
    const float* W    = (const float*)d_in[2];
    const float* bias = (const float*)d_in[3];
    float* out = (float*)d_out;

    (void)in_sizes; (void)n_in; (void)out_size;

    static const size_t smem_bytes = (size_t)(BM + BN) * KP * 4;
    cudaFuncSetAttribute(gemm_kernel,
                         cudaFuncAttributeMaxDynamicSharedMemorySize,
                         (int)smem_bytes);

    detect_kernel<<<1, 256>>>(x);
    sum_emb_kernel<<<M_DIM / 8, 256>>>(x, (const float4*)emb);

    dim3 grid(N_DIM / BN, M_DIM / BM);
    gemm_kernel<<<grid, 512, smem_bytes>>>(W, bias, out);
}

// round 5
// speedup vs baseline: 1.5757x; 1.5757x over previous
#include <cuda_runtime.h>
#include <cstdint>

// Problem constants
#define M_DIM 4096
#define N_DIM 32000
#define K_DIM 128
#define BM 128
#define BN 256
#define KP 132   // padded k-stride in smem words (132 % 32 == 4 -> conflict-free)

// Device scratch
__device__ float g_summed[M_DIM * K_DIM];   // 2 MB, TF32-rounded A
__device__ float g_W[N_DIM * K_DIM];        // 16.4 MB, TF32-rounded W
__device__ int   g_stride;                  // 1 = int32 indices, 2 = int64

__device__ __forceinline__ unsigned f2tf32(float f) {
    unsigned u;
    asm("cvt.rna.tf32.f32 %0, %1;" : "=r"(u) : "f"(f));
    return u;
}

__device__ __forceinline__ void cp16(uint32_t dst, const void* src) {
    asm volatile("cp.async.cg.shared.global [%0], [%1], 16;"
                 :: "r"(dst), "l"(src));
}
template <int N> __device__ __forceinline__ void cp_wait() {
    asm volatile("cp.async.wait_group %0;" :: "n"(N));
}

// ---------------------------------------------------------------------------
// Detect int64 vs int32 index tensor (odd 32-bit words all zero => int64).
// Sample 2048 odd words: P(false positive) ~ (1/32000)^2048.
// ---------------------------------------------------------------------------
__global__ void detect_kernel(const int* __restrict__ x32) {
    __shared__ int any;
    if (threadIdx.x == 0) any = 0;
    __syncthreads();
    int i = 1 + 2 * threadIdx.x;          // odd words < 2048 valid in both layouts
    int v0 = x32[i];
    int v1 = x32[i + 512];
    int v2 = x32[i + 1024];
    int v3 = x32[i + 1536];
    if (v0 | v1 | v2 | v3) any = 1;       // benign race
    __syncthreads();
    if (threadIdx.x == 0) g_stride = any ? 1 : 2;
}

// ---------------------------------------------------------------------------
// Pre-round W to TF32 (enables raw cp.async of B tiles in the GEMM).
// ---------------------------------------------------------------------------
__global__ void round_w_kernel(const float4* __restrict__ W) {
    int i = blockIdx.x * 256 + threadIdx.x;
    float4 v = W[i];
    uint4 u;
    u.x = f2tf32(v.x); u.y = f2tf32(v.y);
    u.z = f2tf32(v.z); u.w = f2tf32(v.w);
    reinterpret_cast<uint4*>(g_W)[i] = u;
}

// ---------------------------------------------------------------------------
// CBOW gather-sum (padding_idx=0 skipped), TF32-rounded output.
// ---------------------------------------------------------------------------
__global__ void sum_emb_kernel(const int* __restrict__ x32,
                               const float4* __restrict__ emb) {
    int sample = blockIdx.x * 8 + (threadIdx.x >> 5);
    int v = threadIdx.x & 31;
    int stride = g_stride;
    float4 s = make_float4(0.f, 0.f, 0.f, 0.f);
#pragma unroll
    for (int c = 0; c < 8; c++) {
        int i = x32[(sample * 8 + c) * stride];
        if (i != 0) {
            float4 t = emb[i * 32 + v];
            s.x += t.x; s.y += t.y; s.z += t.z; s.w += t.w;
        }
    }
    uint4 u;
    u.x = f2tf32(s.x); u.y = f2tf32(s.y);
    u.z = f2tf32(s.z); u.w = f2tf32(s.w);
    reinterpret_cast<uint4*>(g_summed)[sample * 32 + v] = u;
}

// ---------------------------------------------------------------------------
// GEMM: out[M,N] = summed[M,K] @ W[N,K]^T + b
// CTA 128x256, 256 threads, 8 warps (2M x 4N), warp tile 64x64.
// K split into 4 chunks of 32; all chunk loads issued as cp.async groups up
// front, compute on chunk c overlaps the in-flight loads of chunks c+1..3.
// Fragment registers double-buffered across k-steps within a chunk.
// ---------------------------------------------------------------------------
__global__ void __launch_bounds__(256, 1)
gemm_kernel(const float* __restrict__ bias, float* __restrict__ out) {
    extern __shared__ unsigned smem[];
    unsigned* As = smem;              // [128][132]
    unsigned* Bs = smem + BM * KP;    // [256][132]
    const uint32_t sbase = (uint32_t)__cvta_generic_to_shared(smem);

    const int tid = threadIdx.x;
    const int bm = blockIdx.y * BM;
    const int bn = blockIdx.x * BN;

    // ---- issue all 4 K-chunk load groups ----
    const float4* Ag = reinterpret_cast<const float4*>(g_summed) + bm * 32;
    const float4* Bg = reinterpret_cast<const float4*>(g_W) + bn * 32;
#pragma unroll
    for (int c = 0; c < 4; c++) {
#pragma unroll
        for (int t = 0; t < 4; t++) {              // A: 128 rows x 8 float4
            int idx = tid + t * 256;
            int row = idx >> 3, j = (idx & 7) + c * 8;
            cp16(sbase + (row * KP + j * 4) * 4, Ag + row * 32 + j);
        }
#pragma unroll
        for (int t = 0; t < 8; t++) {              // B: 256 rows x 8 float4
            int idx = tid + t * 256;
            int row = idx >> 3, j = (idx & 7) + c * 8;
            cp16(sbase + (BM * KP + row * KP + j * 4) * 4, Bg + row * 32 + j);
        }
        asm volatile("cp.async.commit_group;" ::: "memory");
    }

    const int lane = tid & 31;
    const int warp = tid >> 5;
    const int wm = (warp & 1) * 64;    // 2 warps along M
    const int wn = (warp >> 1) * 64;   // 4 warps along N
    const int g  = lane >> 2;          // 0..7
    const int tg = lane & 3;           // 0..3

    float acc[4][8][4];
#pragma unroll
    for (int mi = 0; mi < 4; mi++)
#pragma unroll
        for (int ni = 0; ni < 8; ni++)
#pragma unroll
            for (int r = 0; r < 4; r++) acc[mi][ni][r] = 0.f;

    unsigned af[2][4][4], bf[2][8][2];

    auto load_frag = [&](int k0, unsigned a[4][4], unsigned b[8][2]) {
#pragma unroll
        for (int mi = 0; mi < 4; mi++) {
            int r0 = (wm + mi * 16 + g) * KP + k0 + tg;
            a[mi][0] = As[r0];
            a[mi][1] = As[r0 + 8 * KP];
            a[mi][2] = As[r0 + 4];
            a[mi][3] = As[r0 + 8 * KP + 4];
        }
#pragma unroll
        for (int ni = 0; ni < 8; ni++) {
            int c0 = (wn + ni * 8 + g) * KP + k0 + tg;
            b[ni][0] = Bs[c0];
            b[ni][1] = Bs[c0 + 4];
        }
    };
    auto mma_tile = [&](unsigned a[4][4], unsigned b[8][2]) {
#pragma unroll
        for (int mi = 0; mi < 4; mi++)
#pragma unroll
            for (int ni = 0; ni < 8; ni++)
                asm volatile(
                    "mma.sync.aligned.m16n8k8.row.col.f32.tf32.tf32.f32 "
                    "{%0,%1,%2,%3}, {%4,%5,%6,%7}, {%8,%9}, {%0,%1,%2,%3};"
                    : "+f"(acc[mi][ni][0]), "+f"(acc[mi][ni][1]),
                      "+f"(acc[mi][ni][2]), "+f"(acc[mi][ni][3])
                    : "r"(a[mi][0]), "r"(a[mi][1]), "r"(a[mi][2]), "r"(a[mi][3]),
                      "r"(b[ni][0]), "r"(b[ni][1]));
    };

#pragma unroll
    for (int c = 0; c < 4; c++) {
        if (c == 0)      cp_wait<3>();
        else if (c == 1) cp_wait<2>();
        else if (c == 2) cp_wait<1>();
        else             cp_wait<0>();
        __syncthreads();

        load_frag(c * 32, af[0], bf[0]);
#pragma unroll
        for (int q = 0; q < 4; q++) {
            int cur = q & 1;
            if (q < 3) load_frag(c * 32 + (q + 1) * 8, af[cur ^ 1], bf[cur ^ 1]);
            mma_tile(af[cur], bf[cur]);
        }
    }

    // Epilogue: bias add + float2 stores. Tiles divide exactly; no bounds checks.
#pragma unroll
    for (int ni = 0; ni < 8; ni++) {
        int col = bn + wn + ni * 8 + 2 * tg;
        float2 bb = *reinterpret_cast<const float2*>(bias + col);
#pragma unroll
        for (int mi = 0; mi < 4; mi++) {
            int row = bm + wm + mi * 16 + g;
            float2 v0 = make_float2(acc[mi][ni][0] + bb.x, acc[mi][ni][1] + bb.y);
            float2 v1 = make_float2(acc[mi][ni][2] + bb.x, acc[mi][ni][3] + bb.y);
            *reinterpret_cast<float2*>(out + (size_t)row * N_DIM + col) = v0;
            *reinterpret_cast<float2*>(out + (size_t)(row + 8) * N_DIM + col) = v1;
        }
    }
}

// ---------------------------------------------------------------------------
extern "C" void kernel_launch(void* const* d_in, const int* in_sizes, int n_in,
                              void* d_out, int out_size) {
    const int*   x    = (const int*)d_in[0];
    const float* emb  = (const float*)d_in[1];
    const float* W    = (const float*)d_in[2];
    const float* bias = (const float*)d_in[3];
    float* out = (float*)d_out;

    (void)in_sizes; (void)n_in; (void)out_size;

    static const size_t smem_bytes = (size_t)(BM + BN) * KP * 4;
    cudaFuncSetAttribute(gemm_kernel,
                         cudaFuncAttributeMaxDynamicSharedMemorySize,
                         (int)smem_bytes);

    detect_kernel<<<1, 256>>>(x);
    round_w_kernel<<<N_DIM * K_DIM / 4 / 256, 256>>>((const float4*)W);
    sum_emb_kernel<<<M_DIM / 8, 256>>>(x, (const float4*)emb);

    dim3 grid(N_DIM / BN, M_DIM / BM);
    gemm_kernel<<<grid, 256, smem_bytes>>>(bias, out);
}